// round 14
// baseline (speedup 1.0000x reference)
#include <cuda_runtime.h>
#include <cuda_fp16.h>
#include <cstdint>

// NRI MLPDecoder. L1 = mma.m16n8k8.tf32 -> C-frags reused as B-frags of
// L2 = mma.m16n8k16.f16 computing z^T (W2^T as A operand); z^T C-frags reused
// as A-frags of the aggregation MMA (R as col-major B, plain ldsm, cached).
// No movmatrix, no msgs smem. k-outer, 2 CTAs/SM.
// B=16,N=30,T=50(49 out),D=4,K=4,H=M=NH=128,E=870 (pad 1024 = 4x256).
// One CTA = one (b,t), 256 threads, grid 784. Warp w owns edges w*32..w*32+31.

typedef unsigned long long ull;

#define NB 16
#define NN 30
#define TFULL 50
#define TOUT 49
#define EDGES 870
#define EPAD 1024
#define NPASS 4
#define EPASS 256
#define THREADS 256
#define GRID (NB*TOUT)

// ---------------- smem byte offsets ----------------
#define SW2   0          // W2^T k-slice fp16 [128 f][136 c] = 34816
#define SPRE  34816      // pre tf32 [256][12] f32 = 12288
#define SW1K  47104      // W1k tf32 [8][136] = 4352
#define SB1   51456      // b1 f32 [4][128] = 2048
#define SB2   53504      // b2 f32 [4][128] = 2048
#define SRTK  55552      // rt_k f32 [1024] = 4096
#define SR    59648      // R fp16 [16 nodes][264] = 8448 (stride 528B)
#define SAGG  68096      // agg f32 [30][132] = 15840
#define SXS   83936      // x f32 [32][4] = 512
#define SOB   84448      // ob1 512 + ob2 512 + ob3 16
#define SMEM_BYTES 85488

// phase-B aliases
#define PB_AUG  0            // [30][132] f32
#define PB_H    16384        // [30][128] f32
#define PB_P0   34816        // [30][128] f32
#define PB_P1   50176        // [30][128] f32 (ends 65536 < SAGG)
#define PB_H2   SAGG         // [30][129] f32

__device__ __align__(16) __half g_W2h[4*128*136];  // W2^T fp16: [k][f][c_pad136]

// ---------------- helpers ----------------
__device__ __forceinline__ uint32_t smem_u32(const void* p){
  uint32_t a; asm("{ .reg .u64 t; cvta.to.shared.u64 t, %1; cvt.u32.u64 %0, t; }" : "=r"(a) : "l"(p));
  return a;
}
__device__ __forceinline__ void cp16(uint32_t dst, const void* src){
  asm volatile("cp.async.ca.shared.global [%0], [%1], 16;" :: "r"(dst), "l"(src));
}
__device__ __forceinline__ void cp_commit(){ asm volatile("cp.async.commit_group;" ::: "memory"); }
__device__ __forceinline__ void cp_wait0(){ asm volatile("cp.async.wait_group 0;" ::: "memory"); }
__device__ __forceinline__ float cvt_tf32(float x){
  float o; asm("cvt.rna.tf32.f32 %0, %1;" : "=f"(o) : "f"(x)); return o;
}
__device__ __forceinline__ void mma16816(float* c,
    uint32_t a0, uint32_t a1, uint32_t a2, uint32_t a3,
    uint32_t b0, uint32_t b1){
  asm volatile("mma.sync.aligned.m16n8k16.row.col.f32.f16.f16.f32 "
    "{%0,%1,%2,%3}, {%4,%5,%6,%7}, {%8,%9}, {%0,%1,%2,%3};"
    : "+f"(c[0]), "+f"(c[1]), "+f"(c[2]), "+f"(c[3])
    : "r"(a0), "r"(a1), "r"(a2), "r"(a3), "r"(b0), "r"(b1));
}
__device__ __forceinline__ void mma_tf32(float* c,
    const uint32_t* a, uint32_t b0, uint32_t b1){
  asm volatile("mma.sync.aligned.m16n8k8.row.col.f32.tf32.tf32.f32 "
    "{%0,%1,%2,%3}, {%4,%5,%6,%7}, {%8,%9}, {%0,%1,%2,%3};"
    : "+f"(c[0]), "+f"(c[1]), "+f"(c[2]), "+f"(c[3])
    : "r"(a[0]), "r"(a[1]), "r"(a[2]), "r"(a[3]), "r"(b0), "r"(b1));
}
__device__ __forceinline__ void ldsm4(uint32_t* r, uint32_t addr){
  asm volatile("ldmatrix.sync.aligned.m8n8.x4.shared.b16 {%0,%1,%2,%3}, [%4];"
    : "=r"(r[0]), "=r"(r[1]), "=r"(r[2]), "=r"(r[3]) : "r"(addr));
}
__device__ __forceinline__ uint32_t relu_pack(float a, float b){
  __half2 h = __floats2half2_rn(a, b);
  __half2 z = __half2half2(__ushort_as_half(0));
  __half2 r = __hmax2(h, z);
  return *(uint32_t*)&r;
}

// ---------------- prep: W2^T -> fp16, padded stride 136 ----------------
__global__ void prep_w2(const float* __restrict__ W2){
  int idx = blockIdx.x * blockDim.x + threadIdx.x;
  if (idx >= 4*128*128) return;
  int k = idx >> 14, rem = idx & 16383;
  int m = rem >> 7, c = rem & 127;
  g_W2h[(k*128 + m)*136 + c] = __float2half(W2[(k*128 + c)*128 + m]);
}

// ---------------- main ----------------
extern __shared__ __align__(16) char smc[];

__global__ __launch_bounds__(THREADS, 2)
void nri_mma_kernel(
    const float* __restrict__ inputs,    // [16,30,50,4]
    const float* __restrict__ rel_type,  // [16,870,4]
    const float* __restrict__ W1,        // [4,8,128]
    const float* __restrict__ b1,        // [4,128]
    const float* __restrict__ b2,        // [4,128]
    const float* __restrict__ oW1,       // [132,128]
    const float* __restrict__ ob1,
    const float* __restrict__ oW2,       // [128,128]
    const float* __restrict__ ob2,
    const float* __restrict__ oW3,       // [128,4]
    const float* __restrict__ ob3,
    float* __restrict__ out)             // [16,30,49,4]
{
  const int tid  = threadIdx.x;
  const int lane = tid & 31;
  const int g    = lane >> 2;
  const int tg   = lane & 3;
  const int wid  = tid >> 5;       // warp owns edges wid*32..wid*32+31 per pass
  const int qq   = lane >> 3;
  const int rr   = lane & 7;
  const int b = blockIdx.x / TOUT;
  const int t = blockIdx.x % TOUT;

  const uint32_t sbase = smem_u32(smc);
  float* PREs = (float*)(smc + SPRE);
  float* W1Ks = (float*)(smc + SW1K);
  float* b1s  = (float*)(smc + SB1);
  float* b2s  = (float*)(smc + SB2);
  float* RTk  = (float*)(smc + SRTK);
  float* AGG  = (float*)(smc + SAGG);
  float* XS   = (float*)(smc + SXS);
  float* ob1s = (float*)(smc + SOB);
  float* ob2s = (float*)(smc + SOB + 512);
  float* ob3s = (float*)(smc + SOB + 1024);

  // ---- prologue ----
  for (int i = tid; i < 128; i += THREADS){
    cp16(sbase + SB1 + i*16, (const char*)b1 + i*16);
    cp16(sbase + SB2 + i*16, (const char*)b2 + i*16);
  }
  cp_commit();
  if (tid < 120){
    int n = tid >> 2, d = tid & 3;
    XS[tid] = inputs[((b*NN + n)*TFULL + t)*4 + d];
  }
  for (int i = tid; i < NN*132; i += THREADS) AGG[i] = 0.f;
  if (tid < 128) ob1s[tid] = ob1[tid];
  else           ob2s[tid-128] = ob2[tid-128];
  if (tid < 4) ob3s[tid] = ob3[tid];
  cp_wait0();

  // ================= relation types (outer) =================
  for (int k = 0; k < 4; k++){
    // ---- stage W2k (fp16), W1k (tf32), rt_k ----
    for (int i = tid; i < 2176; i += THREADS)
      cp16(sbase + SW2 + i*16, (const char*)g_W2h + k*34816 + i*16);
    cp_commit();
    for (int i = tid; i < 1024; i += THREADS)
      W1Ks[(i >> 7)*136 + (i & 127)] = cvt_tf32(W1[k*1024 + i]);
    for (int i = tid; i < EPAD; i += THREADS)
      RTk[i] = (i < EDGES) ? rel_type[(b*EDGES + i)*4 + k] : 0.f;
    cp_wait0();
    __syncthreads();

    const float* b1k = b1s + k*128;
    const float* b2k = b2s + k*128;

    // ---- passes of 256 edges ----
    for (int p = 0; p < NPASS; p++){
      const int pbase = p*EPASS;
      const int n0 = (pbase*565) >> 14;
      const int wlo = pbase + wid*32, whi = wlo + 31;

      // ---- build PRE tf32 [256][12] (thread = edge) ----
      {
        const int ge = pbase + tid;
        float4 rv = make_float4(0.f,0.f,0.f,0.f), sv = rv;
        if (ge < EDGES){
          int n = (ge*565) >> 14;
          int idx = ge - n*29;
          int s = idx + (idx >= n ? 1 : 0);
          rv = *(const float4*)(XS + n*4);
          sv = *(const float4*)(XS + s*4);
        }
        float* pr = PREs + tid*12;
        *(float4*)(pr)   = make_float4(cvt_tf32(rv.x),cvt_tf32(rv.y),cvt_tf32(rv.z),cvt_tf32(rv.w));
        *(float4*)(pr+4) = make_float4(cvt_tf32(sv.x),cvt_tf32(sv.y),cvt_tf32(sv.z),cvt_tf32(sv.w));
      }
      // ---- build R fp16 [16][264 stride]: R[row][e] = rt iff recv==n0+row ----
      #pragma unroll
      for (int it = 0; it < 8; it++){
        const int idx = tid + it*256;           // 2048 half2 entries
        const int row = idx >> 7, pr2 = idx & 127;
        const int e = pr2*2, geA = pbase + e;
        const int nA = (geA*565) >> 14, nB2 = ((geA+1)*565) >> 14;
        const float vA = (nA  == n0 + row) ? RTk[geA]   : 0.f;
        const float vB = (nB2 == n0 + row) ? RTk[geA+1] : 0.f;
        *(__half2*)(smc + SR + row*528 + e*2) = __floats2half2_rn(vA, vB);
      }
      __syncthreads();   // PRE + R ready

      // ---- per-pass node flags + row pointers (hoisted out of strips) ----
      int tchm = 0, excm = 0;
      float* prow[4];
      #pragma unroll
      for (int ii = 0; ii < 4; ii++){
        const int nd = (ii >> 1)*8 + tg*2 + (ii & 1);
        const int row = n0 + nd;
        const int rc = (row < NN) ? row : 0;
        prow[ii] = AGG + rc*132 + g;
        const int er0 = row*29, er1 = er0 + 28;
        const bool tc = (row < NN) && (er1 >= wlo) && (er0 <= whi);
        const int plo = (er0 > pbase) ? er0 : pbase;
        const int phi = (er1 < pbase + 255) ? er1 : pbase + 255;
        const bool ex = (plo >= wlo) && (phi <= whi);
        tchm |= ((int)tc) << ii;
        excm |= ((int)ex) << ii;
      }

      // ---- R B-frags (col-major [k=edge][n=node]) cached for the pass ----
      uint32_t bt[2][4];
      #pragma unroll
      for (int kg = 0; kg < 2; kg++)
        ldsm4(bt[kg], sbase + SR + ((qq >> 1)*8 + rr)*528 + (qq & 1)*16
                    + (wid*32 + kg*16)*2);

      // ---- layer 1: tf32 MMA -> relu -> fp16 frags (B-frags of L2) ----
      uint32_t af[2][8][4];
      #pragma unroll
      for (int rb = 0; rb < 2; rb++){
        const int r0 = wid*32 + rb*16;
        uint32_t za[4];
        const uint32_t* PB = (const uint32_t*)PREs;
        za[0] = PB[(r0 + g)*12 + tg];
        za[1] = PB[(r0 + 8 + g)*12 + tg];
        za[2] = PB[(r0 + g)*12 + tg + 4];
        za[3] = PB[(r0 + 8 + g)*12 + tg + 4];
        const uint32_t* WB = (const uint32_t*)W1Ks;
        #pragma unroll
        for (int ks = 0; ks < 8; ks++){
          float za1[4], zb1[4];
          {
            const float2 bpA = *(const float2*)(b1k + (2*ks)*8 + tg*2);
            const float2 bpB = *(const float2*)(b1k + (2*ks+1)*8 + tg*2);
            za1[0]=bpA.x; za1[1]=bpA.y; za1[2]=bpA.x; za1[3]=bpA.y;
            zb1[0]=bpB.x; zb1[1]=bpB.y; zb1[2]=bpB.x; zb1[3]=bpB.y;
          }
          {
            const int colA = (2*ks)*8 + g, colB = (2*ks+1)*8 + g;
            mma_tf32(za1, za, WB[tg*136 + colA], WB[(tg+4)*136 + colA]);
            mma_tf32(zb1, za, WB[tg*136 + colB], WB[(tg+4)*136 + colB]);
          }
          // af[rb][ks][0]: h1[e=rb16+g][c=16ks+tg*2..], [1]: e+8, [2]: c+8, [3]: e+8,c+8
          af[rb][ks][0] = relu_pack(za1[0], za1[1]);
          af[rb][ks][1] = relu_pack(za1[2], za1[3]);
          af[rb][ks][2] = relu_pack(zb1[0], zb1[1]);
          af[rb][ks][3] = relu_pack(zb1[2], zb1[3]);
        }
      }

      // ---- f-strips: z^T = W2^T(A) @ h1^T(B=af), then agg = relu(z^T)(A) @ R^T(B) ----
      const uint32_t wbase = sbase + SW2 + (uint32_t)((lane & 15)*272 + (lane >> 4)*16);
      #pragma unroll 1
      for (int s = 0; s < 8; s++){
        // z^T init = b2 broadcast along edges; rows f = s*16+g, s*16+8+g
        float z[4][4];
        {
          const float bg0 = b2k[s*16 + g];
          const float bg1 = b2k[s*16 + 8 + g];
          #pragma unroll
          for (int nb = 0; nb < 4; nb++){
            z[nb][0]=bg0; z[nb][1]=bg0; z[nb][2]=bg1; z[nb][3]=bg1;
          }
        }
        {
          const uint32_t wrow = wbase + (uint32_t)(s*16*272);
          #pragma unroll
          for (int ks = 0; ks < 8; ks++){
            uint32_t wf[4];
            ldsm4(wf, wrow + ks*32);
            mma16816(z[0], wf[0],wf[1],wf[2],wf[3], af[0][ks][0], af[0][ks][2]);
            mma16816(z[1], wf[0],wf[1],wf[2],wf[3], af[0][ks][1], af[0][ks][3]);
            mma16816(z[2], wf[0],wf[1],wf[2],wf[3], af[1][ks][0], af[1][ks][2]);
            mma16816(z[3], wf[0],wf[1],wf[2],wf[3], af[1][ks][1], af[1][ks][3]);
          }
        }
        // aggregation: cagg[ng] = relu(z^T) @ R^T  (K = 32 edges, 2 k-groups)
        float cagg[2][4];
        #pragma unroll
        for (int ng = 0; ng < 2; ng++)
          #pragma unroll
          for (int r2 = 0; r2 < 4; r2++) cagg[ng][r2] = 0.f;
        #pragma unroll
        for (int kg = 0; kg < 2; kg++){
          const uint32_t a0 = relu_pack(z[kg*2][0],   z[kg*2][1]);
          const uint32_t a1 = relu_pack(z[kg*2][2],   z[kg*2][3]);
          const uint32_t a2 = relu_pack(z[kg*2+1][0], z[kg*2+1][1]);
          const uint32_t a3 = relu_pack(z[kg*2+1][2], z[kg*2+1][3]);
          mma16816(cagg[0], a0,a1,a2,a3, bt[kg][0], bt[kg][1]);
          mma16816(cagg[1], a0,a1,a2,a3, bt[kg][2], bt[kg][3]);
        }
        // apply: AGG[node][f], f = s*16+g (+8); flags hoisted
        #pragma unroll
        for (int ng = 0; ng < 2; ng++)
          #pragma unroll
          for (int jj = 0; jj < 2; jj++){
            const int ii = ng*2 + jj;
            if ((tchm >> ii) & 1){
              float* pp = prow[ii] + s*16;
              const float v0 = cagg[ng][jj], v1 = cagg[ng][jj+2];
              if ((excm >> ii) & 1){
                pp[0] += v0; pp[8] += v1;
              } else {
                atomicAdd(pp,     v0);
                atomicAdd(pp + 8, v1);
              }
            }
          }
      }
      __syncthreads();   // pass done: PRE/R reusable, AGG ordered vs next pass
    }
  }

  // ================= node MLP (weight-stationary, i-split halves) =========
  float* AUG = (float*)(smc + PB_AUG);   // [30][132]
  float* H   = (float*)(smc + PB_H);     // [30][128]
  float* H2  = (float*)(smc + PB_H2);    // [30][129]
  float* P0  = (float*)(smc + PB_P0);
  float* P1  = (float*)(smc + PB_P1);

  for (int idx = tid; idx < NN*132; idx += THREADS){
    int n = idx / 132, i = idx - n*132;
    AUG[idx] = (i < 4) ? XS[n*4 + i] : AGG[n*132 + (i - 4)];
  }
  __syncthreads();
  { // layer 1: P[half] = aug @ oW1 (i-range split)
    const int f = tid & 127, half = tid >> 7;
    const int i0 = half ? 66 : 0, i1 = half ? 132 : 66;
    float acc[NN];
    #pragma unroll
    for (int n = 0; n < NN; n++) acc[n] = 0.f;
    for (int i = i0; i < i1; i++){
      const float w = oW1[i*128 + f];
      #pragma unroll
      for (int n = 0; n < NN; n++) acc[n] += AUG[n*132 + i] * w;
    }
    float* P = half ? P1 : P0;
    #pragma unroll
    for (int n = 0; n < NN; n++) P[n*128 + f] = acc[n];
  }
  __syncthreads();
  for (int idx = tid; idx < NN*128; idx += THREADS)
    H[idx] = fmaxf(P0[idx] + P1[idx] + ob1s[idx & 127], 0.f);
  __syncthreads();
  { // layer 2
    const int f = tid & 127, half = tid >> 7;
    const int i0 = half ? 64 : 0, i1 = half ? 128 : 64;
    float acc[NN];
    #pragma unroll
    for (int n = 0; n < NN; n++) acc[n] = 0.f;
    for (int i = i0; i < i1; i++){
      const float w = oW2[i*128 + f];
      #pragma unroll
      for (int n = 0; n < NN; n++) acc[n] += H[n*128 + i] * w;
    }
    float* P = half ? P1 : P0;
    #pragma unroll
    for (int n = 0; n < NN; n++) P[n*128 + f] = acc[n];
  }
  __syncthreads();
  for (int idx = tid; idx < NN*128; idx += THREADS){
    int n = idx >> 7, f = idx & 127;
    H2[n*129 + f] = fmaxf(P0[idx] + P1[idx] + ob2s[f], 0.f);
  }
  __syncthreads();
  if (tid < NN*4){ // layer 3 + residual
    const int n = tid >> 2, d = tid & 3;
    float a = ob3s[d];
    #pragma unroll 8
    for (int j = 0; j < 128; j++) a += H2[n*129 + j] * oW3[j*4 + d];
    out[((b*NN + n)*TOUT + t)*4 + d] = XS[n*4 + d] + a;
  }
}

extern "C" void kernel_launch(void* const* d_in, const int* in_sizes, int n_in,
                              void* d_out, int out_size) {
  (void)in_sizes; (void)n_in; (void)out_size;
  const float* inputs   = (const float*)d_in[0];
  const float* rel_type = (const float*)d_in[1];
  const float* W1  = (const float*)d_in[4];
  const float* b1  = (const float*)d_in[5];
  const float* W2  = (const float*)d_in[6];
  const float* b2  = (const float*)d_in[7];
  const float* oW1 = (const float*)d_in[8];
  const float* ob1 = (const float*)d_in[9];
  const float* oW2 = (const float*)d_in[10];
  const float* ob2 = (const float*)d_in[11];
  const float* oW3 = (const float*)d_in[12];
  const float* ob3 = (const float*)d_in[13];
  float* out = (float*)d_out;

  prep_w2<<<256, 256>>>(W2);

  cudaFuncSetAttribute(nri_mma_kernel,
                       cudaFuncAttributeMaxDynamicSharedMemorySize, SMEM_BYTES);
  nri_mma_kernel<<<GRID, THREADS, SMEM_BYTES>>>(
      inputs, rel_type, W1, b1, b2, oW1, ob1, oW2, ob2, oW3, ob3, out);
}

// round 15
// speedup vs baseline: 1.0783x; 1.0783x over previous
#include <cuda_runtime.h>
#include <cuda_fp16.h>
#include <cstdint>

// NRI MLPDecoder. L1 = mma.m16n8k8.tf32 (C-frags -> B-frags of L2, in reg),
// L2 = z^T = W2(A, ldsm) @ h1^T(B = af)  [mma.m16n8k16.f16],
// agg = relu(z^T)(A, in reg) @ R^T(B, ldsm once/tile) -> sparse atomicAdd AGG.
// No msgs smem buffer; 2 syncs/tile; 3 CTAs/SM (73.5KB smem, <=80 regs).
// B=16,N=30,T=50(49 out),D=4,K=4,H=M=NH=128,E=870 (pad 896 = 7x128).
// One CTA = one (b,t), 256 threads, grid 784. Warp w owns edges w*16..w*16+15.

typedef unsigned long long ull;

#define NB 16
#define NN 30
#define TFULL 50
#define TOUT 49
#define EDGES 870
#define EPAD 896
#define NTILE 7
#define THREADS 256
#define GRID (NB*TOUT)

// ---------------- smem byte offsets ----------------
#define SW2   0          // W2^T k-slice fp16 [128 f][136 c] = 34816
#define SPRE  34816      // pre tf32 [128][12] f32 = 6144
#define SW1K  40960      // W1k tf32 [8][136] = 4352
#define SB1   45312      // b1 f32 [4][128] = 2048
#define SB2   47360      // b2 f32 [4][128] = 2048
#define SRTK  49408      // rt_k f32 [896] = 3584
#define SR    52992      // R fp16 [16 nodes][136] = 4352 (stride 272B)
#define SAGG  57344      // agg f32 [30][132] = 15840
#define SXS   73184      // x f32 [32][4] = 512
#define SOB   73696      // ob1 512 + ob2 512 + ob3 16 = 1040
#define SMEM_BYTES 74752

// phase-B aliases (phase-A regions dead; AGG consumed into AUG first)
#define PB_AUG  0            // [30][132] f32 = 15840
#define PB_H    16384        // [30][128] f32 = 15360
#define PB_P0   32768        // [30][128] f32
#define PB_P1   49152        // [30][128] f32 (ends 64512 < SXS)
#define PB_H2   0            // [30][129] f32 (AUG dead by then)

__device__ __align__(16) __half g_W2h[4*128*136];  // W2^T fp16: [k][f][c_pad136]

// ---------------- helpers ----------------
__device__ __forceinline__ uint32_t smem_u32(const void* p){
  uint32_t a; asm("{ .reg .u64 t; cvta.to.shared.u64 t, %1; cvt.u32.u64 %0, t; }" : "=r"(a) : "l"(p));
  return a;
}
__device__ __forceinline__ void cp16(uint32_t dst, const void* src){
  asm volatile("cp.async.ca.shared.global [%0], [%1], 16;" :: "r"(dst), "l"(src));
}
__device__ __forceinline__ void cp_commit(){ asm volatile("cp.async.commit_group;" ::: "memory"); }
__device__ __forceinline__ void cp_wait0(){ asm volatile("cp.async.wait_group 0;" ::: "memory"); }
__device__ __forceinline__ float cvt_tf32(float x){
  float o; asm("cvt.rna.tf32.f32 %0, %1;" : "=f"(o) : "f"(x)); return o;
}
__device__ __forceinline__ void mma16816(float* c,
    uint32_t a0, uint32_t a1, uint32_t a2, uint32_t a3,
    uint32_t b0, uint32_t b1){
  asm volatile("mma.sync.aligned.m16n8k16.row.col.f32.f16.f16.f32 "
    "{%0,%1,%2,%3}, {%4,%5,%6,%7}, {%8,%9}, {%0,%1,%2,%3};"
    : "+f"(c[0]), "+f"(c[1]), "+f"(c[2]), "+f"(c[3])
    : "r"(a0), "r"(a1), "r"(a2), "r"(a3), "r"(b0), "r"(b1));
}
__device__ __forceinline__ void mma_tf32(float* c,
    const uint32_t* a, uint32_t b0, uint32_t b1){
  asm volatile("mma.sync.aligned.m16n8k8.row.col.f32.tf32.tf32.f32 "
    "{%0,%1,%2,%3}, {%4,%5,%6,%7}, {%8,%9}, {%0,%1,%2,%3};"
    : "+f"(c[0]), "+f"(c[1]), "+f"(c[2]), "+f"(c[3])
    : "r"(a[0]), "r"(a[1]), "r"(a[2]), "r"(a[3]), "r"(b0), "r"(b1));
}
__device__ __forceinline__ void ldsm4(uint32_t* r, uint32_t addr){
  asm volatile("ldmatrix.sync.aligned.m8n8.x4.shared.b16 {%0,%1,%2,%3}, [%4];"
    : "=r"(r[0]), "=r"(r[1]), "=r"(r[2]), "=r"(r[3]) : "r"(addr));
}
__device__ __forceinline__ uint32_t relu_pack(float a, float b){
  __half2 h = __floats2half2_rn(a, b);
  __half2 z = __half2half2(__ushort_as_half(0));
  __half2 r = __hmax2(h, z);
  return *(uint32_t*)&r;
}

// ---------------- prep: W2^T -> fp16, padded stride 136 ----------------
__global__ void prep_w2(const float* __restrict__ W2){
  int idx = blockIdx.x * blockDim.x + threadIdx.x;
  if (idx >= 4*128*128) return;
  int k = idx >> 14, rem = idx & 16383;
  int m = rem >> 7, c = rem & 127;
  g_W2h[(k*128 + m)*136 + c] = __float2half(W2[(k*128 + c)*128 + m]);
}

// ---------------- main ----------------
extern __shared__ __align__(16) char smc[];

__global__ __launch_bounds__(THREADS, 3)
void nri_mma_kernel(
    const float* __restrict__ inputs,    // [16,30,50,4]
    const float* __restrict__ rel_type,  // [16,870,4]
    const float* __restrict__ W1,        // [4,8,128]
    const float* __restrict__ b1,        // [4,128]
    const float* __restrict__ b2,        // [4,128]
    const float* __restrict__ oW1,       // [132,128]
    const float* __restrict__ ob1,
    const float* __restrict__ oW2,       // [128,128]
    const float* __restrict__ ob2,
    const float* __restrict__ oW3,       // [128,4]
    const float* __restrict__ ob3,
    float* __restrict__ out)             // [16,30,49,4]
{
  const int tid  = threadIdx.x;
  const int lane = tid & 31;
  const int g    = lane >> 2;
  const int tg   = lane & 3;
  const int wid  = tid >> 5;       // warp owns tile edges wid*16..wid*16+15
  const int qq   = lane >> 3;
  const int rr   = lane & 7;
  const int b = blockIdx.x / TOUT;
  const int t = blockIdx.x % TOUT;

  const uint32_t sbase = smem_u32(smc);
  float* PREs = (float*)(smc + SPRE);
  float* W1Ks = (float*)(smc + SW1K);
  float* b1s  = (float*)(smc + SB1);
  float* b2s  = (float*)(smc + SB2);
  float* RTk  = (float*)(smc + SRTK);
  float* AGG  = (float*)(smc + SAGG);
  float* XS   = (float*)(smc + SXS);
  float* ob1s = (float*)(smc + SOB);
  float* ob2s = (float*)(smc + SOB + 512);
  float* ob3s = (float*)(smc + SOB + 1024);

  // ---- prologue ----
  for (int i = tid; i < 128; i += THREADS){
    cp16(sbase + SB1 + i*16, (const char*)b1 + i*16);
    cp16(sbase + SB2 + i*16, (const char*)b2 + i*16);
  }
  cp_commit();
  if (tid < 120){
    int n = tid >> 2, d = tid & 3;
    XS[tid] = inputs[((b*NN + n)*TFULL + t)*4 + d];
  }
  for (int i = tid; i < NN*132; i += THREADS) AGG[i] = 0.f;
  if (tid < 128) ob1s[tid] = ob1[tid];
  else           ob2s[tid-128] = ob2[tid-128];
  if (tid < 4) ob3s[tid] = ob3[tid];
  cp_wait0();

  // ================= relation types (outer) =================
  for (int k = 0; k < 4; k++){
    // ---- stage W2k (fp16), W1k (tf32), rt_k ----
    for (int i = tid; i < 2176; i += THREADS)
      cp16(sbase + SW2 + i*16, (const char*)g_W2h + k*34816 + i*16);
    cp_commit();
    for (int i = tid; i < 1024; i += THREADS)
      W1Ks[(i >> 7)*136 + (i & 127)] = cvt_tf32(W1[k*1024 + i]);
    for (int i = tid; i < EPAD; i += THREADS)
      RTk[i] = (i < EDGES) ? rel_type[(b*EDGES + i)*4 + k] : 0.f;
    cp_wait0();
    __syncthreads();

    const float* b1k = b1s + k*128;
    const float* b2k = b2s + k*128;

    // ---- edge tiles of 128 ----
    for (int m = 0; m < NTILE; m++){
      const int gbase = m*128;
      const int n0 = (gbase*565) >> 14;
      const int wlo = gbase + wid*16;

      // ---- build PRE tf32 [128][12] ----
      {
        const int e1 = tid >> 1, half = tid & 1;
        const int ge = gbase + e1;
        float4 v = make_float4(0.f, 0.f, 0.f, 0.f);
        if (ge < EDGES){
          int n = (ge*565) >> 14;
          int idx = ge - n*29;
          int s = idx + (idx >= n ? 1 : 0);
          v = *(const float4*)(XS + (half ? s : n)*4);
        }
        *(float4*)(PREs + e1*12 + half*4) =
          make_float4(cvt_tf32(v.x), cvt_tf32(v.y), cvt_tf32(v.z), cvt_tf32(v.w));
      }
      // ---- build R fp16 [16][136]: R[row][e] = rt iff recv==n0+row ----
      #pragma unroll
      for (int it = 0; it < 4; it++){
        const int idx = tid + it*256;           // 1024 half2 entries
        const int row = idx >> 6, pr2 = idx & 63;
        const int e = pr2*2, geA = gbase + e;
        const int nA = (geA*565) >> 14, nB2 = ((geA+1)*565) >> 14;
        const float vA = (nA  == n0 + row) ? RTk[geA]   : 0.f;
        const float vB = (nB2 == n0 + row) ? RTk[geA+1] : 0.f;
        *(__half2*)(smc + SR + row*272 + e*2) = __floats2half2_rn(vA, vB);
      }
      __syncthreads();   // PRE + R ready

      // ---- per-lane node flags + row pointers ----
      int tch = 0;
      float* prow[4];
      #pragma unroll
      for (int ii = 0; ii < 4; ii++){
        const int nd = (ii >> 1)*8 + tg*2 + (ii & 1);
        const int row = n0 + nd;
        const int rc = (row < NN) ? row : 0;
        prow[ii] = AGG + rc*132 + g;
        const int er0 = row*29, er1 = er0 + 28;
        const bool tc = (row < NN) && (er1 >= wlo) && (er0 <= wlo + 15);
        tch |= ((int)tc) << ii;
      }

      // ---- R B-frags for warp's 16 edges (cached across strips) ----
      uint32_t bt[4];
      ldsm4(bt, sbase + SR + ((qq >> 1)*8 + rr)*272 + (qq & 1)*16 + (wid*16)*2);

      // ---- layer 1: tf32 MMA -> relu -> fp16 frags (B-frags of L2) ----
      uint32_t af[8][4];
      {
        const int r0 = wid*16;
        uint32_t za[4];
        const uint32_t* PB = (const uint32_t*)PREs;
        za[0] = PB[(r0 + g)*12 + tg];
        za[1] = PB[(r0 + 8 + g)*12 + tg];
        za[2] = PB[(r0 + g)*12 + tg + 4];
        za[3] = PB[(r0 + 8 + g)*12 + tg + 4];
        const uint32_t* WB = (const uint32_t*)W1Ks;
        #pragma unroll
        for (int ks = 0; ks < 8; ks++){
          float za1[4], zb1[4];
          {
            const float2 bpA = *(const float2*)(b1k + (2*ks)*8 + tg*2);
            const float2 bpB = *(const float2*)(b1k + (2*ks+1)*8 + tg*2);
            za1[0]=bpA.x; za1[1]=bpA.y; za1[2]=bpA.x; za1[3]=bpA.y;
            zb1[0]=bpB.x; zb1[1]=bpB.y; zb1[2]=bpB.x; zb1[3]=bpB.y;
          }
          {
            const int colA = (2*ks)*8 + g, colB = (2*ks+1)*8 + g;
            mma_tf32(za1, za, WB[tg*136 + colA], WB[(tg+4)*136 + colA]);
            mma_tf32(zb1, za, WB[tg*136 + colB], WB[(tg+4)*136 + colB]);
          }
          // af[ks][0]: h1[e=g][c=16ks+2tg..], [1]: e=8+g, [2]: c+8, [3]: both
          af[ks][0] = relu_pack(za1[0], za1[1]);
          af[ks][1] = relu_pack(za1[2], za1[3]);
          af[ks][2] = relu_pack(zb1[0], zb1[1]);
          af[ks][3] = relu_pack(zb1[2], zb1[3]);
        }
      }

      // ---- f-strips: z^T = W2(A) @ h1^T(B=af); agg = relu(z^T)(A) @ R^T(B) ----
      const uint32_t wbase = sbase + SW2 + (uint32_t)((lane & 15)*272 + (lane >> 4)*16);
      #pragma unroll 1
      for (int s = 0; s < 8; s++){
        // z^T rows f = s*16+g, +8; cols = warp's 16 edges (2 n-groups)
        float z0[4], z1[4];
        {
          const float bg0 = b2k[s*16 + g];
          const float bg1 = b2k[s*16 + 8 + g];
          z0[0]=bg0; z0[1]=bg0; z0[2]=bg1; z0[3]=bg1;
          z1[0]=bg0; z1[1]=bg0; z1[2]=bg1; z1[3]=bg1;
        }
        {
          const uint32_t wrow = wbase + (uint32_t)(s*16*272);
          #pragma unroll
          for (int ks = 0; ks < 8; ks++){
            uint32_t wf[4];
            ldsm4(wf, wrow + ks*32);
            mma16816(z0, wf[0],wf[1],wf[2],wf[3], af[ks][0], af[ks][2]);  // e 0-7
            mma16816(z1, wf[0],wf[1],wf[2],wf[3], af[ks][1], af[ks][3]);  // e 8-15
          }
        }
        // agg MMA: A = relu(z^T) [f][e] (K = 16 edges), B = R^T (bt)
        const uint32_t a0 = relu_pack(z0[0], z0[1]);
        const uint32_t a1 = relu_pack(z0[2], z0[3]);
        const uint32_t a2 = relu_pack(z1[0], z1[1]);
        const uint32_t a3 = relu_pack(z1[2], z1[3]);
        float cagg[2][4];
        #pragma unroll
        for (int ng = 0; ng < 2; ng++)
          #pragma unroll
          for (int r2 = 0; r2 < 4; r2++) cagg[ng][r2] = 0.f;
        mma16816(cagg[0], a0,a1,a2,a3, bt[0], bt[1]);   // nodes n0+0..7
        mma16816(cagg[1], a0,a1,a2,a3, bt[2], bt[3]);   // nodes n0+8..15
        // apply: C[f][node]; lane holds f = s*16+g (+8), nodes tg*2+{0,1}(+8)
        #pragma unroll
        for (int ii = 0; ii < 4; ii++){
          if ((tch >> ii) & 1){
            float* pp = prow[ii] + s*16;
            atomicAdd(pp,     cagg[ii >> 1][ii & 1]);
            atomicAdd(pp + 8, cagg[ii >> 1][(ii & 1) + 2]);
          }
        }
      }
      __syncthreads();   // tile done: PRE/R reusable; W2 restage safe at k end
    }
  }

  // ================= node MLP (weight-stationary, i-split halves) =========
  float* AUG = (float*)(smc + PB_AUG);   // [30][132]
  float* H   = (float*)(smc + PB_H);     // [30][128]
  float* H2  = (float*)(smc + PB_H2);    // [30][129] (over AUG, dead then)
  float* P0  = (float*)(smc + PB_P0);
  float* P1  = (float*)(smc + PB_P1);

  for (int idx = tid; idx < NN*132; idx += THREADS){
    int n = idx / 132, i = idx - n*132;
    AUG[idx] = (i < 4) ? XS[n*4 + i] : AGG[n*132 + (i - 4)];
  }
  __syncthreads();
  { // layer 1: P[half] = aug @ oW1 (i-range split)
    const int f = tid & 127, half = tid >> 7;
    const int i0 = half ? 66 : 0, i1 = half ? 132 : 66;
    float acc[NN];
    #pragma unroll
    for (int n = 0; n < NN; n++) acc[n] = 0.f;
    for (int i = i0; i < i1; i++){
      const float w = oW1[i*128 + f];
      #pragma unroll
      for (int n = 0; n < NN; n++) acc[n] += AUG[n*132 + i] * w;
    }
    float* P = half ? P1 : P0;
    #pragma unroll
    for (int n = 0; n < NN; n++) P[n*128 + f] = acc[n];
  }
  __syncthreads();
  for (int idx = tid; idx < NN*128; idx += THREADS)
    H[idx] = fmaxf(P0[idx] + P1[idx] + ob1s[idx & 127], 0.f);
  __syncthreads();
  { // layer 2
    const int f = tid & 127, half = tid >> 7;
    const int i0 = half ? 64 : 0, i1 = half ? 128 : 64;
    float acc[NN];
    #pragma unroll
    for (int n = 0; n < NN; n++) acc[n] = 0.f;
    for (int i = i0; i < i1; i++){
      const float w = oW2[i*128 + f];
      #pragma unroll
      for (int n = 0; n < NN; n++) acc[n] += H[n*128 + i] * w;
    }
    float* P = half ? P1 : P0;
    #pragma unroll
    for (int n = 0; n < NN; n++) P[n*128 + f] = acc[n];
  }
  __syncthreads();
  for (int idx = tid; idx < NN*128; idx += THREADS){
    int n = idx >> 7, f = idx & 127;
    H2[n*129 + f] = fmaxf(P0[idx] + P1[idx] + ob2s[f], 0.f);
  }
  __syncthreads();
  if (tid < NN*4){ // layer 3 + residual
    const int n = tid >> 2, d = tid & 3;
    float a = ob3s[d];
    #pragma unroll 8
    for (int j = 0; j < 128; j++) a += H2[n*129 + j] * oW3[j*4 + d];
    out[((b*NN + n)*TOUT + t)*4 + d] = XS[n*4 + d] + a;
  }
}

extern "C" void kernel_launch(void* const* d_in, const int* in_sizes, int n_in,
                              void* d_out, int out_size) {
  (void)in_sizes; (void)n_in; (void)out_size;
  const float* inputs   = (const float*)d_in[0];
  const float* rel_type = (const float*)d_in[1];
  const float* W1  = (const float*)d_in[4];
  const float* b1  = (const float*)d_in[5];
  const float* W2  = (const float*)d_in[6];
  const float* b2  = (const float*)d_in[7];
  const float* oW1 = (const float*)d_in[8];
  const float* ob1 = (const float*)d_in[9];
  const float* oW2 = (const float*)d_in[10];
  const float* ob2 = (const float*)d_in[11];
  const float* oW3 = (const float*)d_in[12];
  const float* ob3 = (const float*)d_in[13];
  float* out = (float*)d_out;

  prep_w2<<<256, 256>>>(W2);

  cudaFuncSetAttribute(nri_mma_kernel,
                       cudaFuncAttributeMaxDynamicSharedMemorySize, SMEM_BYTES);
  nri_mma_kernel<<<GRID, THREADS, SMEM_BYTES>>>(
      inputs, rel_type, W1, b1, b2, oW1, ob1, oW2, ob2, oW3, ob3, out);
}